// round 15
// baseline (speedup 1.0000x reference)
#include <cuda_runtime.h>
#include <cuda_bf16.h>
#include <cooperative_groups.h>
#include <cstdint>

namespace cg = cooperative_groups;

#define BB 32
#define TT 2048
#define DD 256
#define HH 256
#define G4 1024
#define KK 8

__device__ float g_G[(size_t)2 * BB * TT * G4];
__device__ float g_h[(size_t)2 * BB * TT * HH];
__device__ float g_emis[(size_t)BB * TT * KK];
__device__ float g_res[BB];

__device__ __forceinline__ uint32_t cvta_s(const void* p) {
    return (uint32_t)__cvta_generic_to_shared(p);
}

#define FMA2(acc, a, b) asm("fma.rn.f32x2 %0, %1, %2, %0;" : "+l"(acc) : "l"(a), "l"(b))
#define ADD2(d, a, b)   asm("add.rn.f32x2 %0, %1, %2;" : "=l"(d) : "l"(a), "l"(b))
#define PACK2(d, s)     asm("mov.b64 %0, {%1, %1};" : "=l"(d) : "f"(s))
#define PACKP(d, lo, hi) asm("mov.b64 %0, {%1, %2};" : "=l"(d) : "f"(lo), "f"(hi))
#define UNPACK2(lo, hi, v) asm("mov.b64 {%0, %1}, %2;" : "=f"(lo), "=f"(hi) : "l"(v))
#define LDS_V2U64(a, b, addr) \
    asm("ld.shared.v2.b64 {%0, %1}, [%2];" : "=l"(a), "=l"(b) : "r"(addr))
#define LDS_V4F32(w0, w1, w2, w3, addr) \
    asm("ld.shared.v4.f32 {%0, %1, %2, %3}, [%4];" \
        : "=f"(w0), "=f"(w1), "=f"(w2), "=f"(w3) : "r"(addr))

#define MBAR_INIT(addr, cnt) \
    asm volatile("mbarrier.init.shared.b64 [%0], %1;" :: "r"(addr), "r"(cnt) : "memory")
#define MBAR_ARRIVE_EXPECT(addr, bytes) \
    asm volatile("mbarrier.arrive.expect_tx.shared.b64 _, [%0], %1;" \
                 :: "r"(addr), "r"(bytes) : "memory")
#define ST_ASYNC_B64(raddr, val, rmbar) \
    asm volatile("st.async.shared::cluster.mbarrier::complete_tx::bytes.b64 [%0], %1, [%2];" \
                 :: "r"(raddr), "l"(val), "r"(rmbar) : "memory")
#define MAPA(dst, laddr, rank) \
    asm("mapa.shared::cluster.u32 %0, %1, %2;" : "=r"(dst) : "r"(laddr), "r"(rank))

__device__ __forceinline__ void mbar_wait(uint32_t mbar, uint32_t parity) {
    uint32_t done;
    asm volatile(
        "{\n\t.reg .pred p;\n\t"
        "mbarrier.try_wait.parity.acquire.cta.shared::cta.b64 p, [%1], %2;\n\t"
        "selp.b32 %0, 1, 0, p;\n\t}"
        : "=r"(done) : "r"(mbar), "r"(parity) : "memory");
    if (!done) {
        asm volatile(
            "{\n\t.reg .pred P1;\n\t"
            "WL_%=:\n\t"
            "mbarrier.try_wait.parity.acquire.cta.shared::cta.b64 P1, [%0], %1, 0x989680;\n\t"
            "@P1 bra.uni WD_%=;\n\t"
            "bra.uni WL_%=;\n\t"
            "WD_%=:\n\t}"
            :: "r"(mbar), "r"(parity) : "memory");
    }
}

__device__ __forceinline__ float sigf(float x)   { return 1.0f / (1.0f + __expf(-x)); }
__device__ __forceinline__ float tanhf2(float x) { return 2.0f / (1.0f + __expf(-2.0f * x)) - 1.0f; }

// ---------------- Kernel 1: input projection GEMM (f32x2) + tile elision ----------------
__global__ void __launch_bounds__(256, 3) proj_kernel(
    const float* __restrict__ x,
    const float* __restrict__ wf, const float* __restrict__ bif, const float* __restrict__ bhf,
    const float* __restrict__ wb, const float* __restrict__ bib, const float* __restrict__ bhb,
    const int* __restrict__ lengths)
{
    __shared__ float sA[32 * 132];
    __shared__ float sB[32 * 68];

    const int dir = blockIdx.z;
    const int bM = blockIdx.x * 128;

    // tile elision: tile covers batch bb, t in [t0, t0+128)
    {
        const int bb = bM >> 11;
        const int t0 = bM & 2047;
        if (dir == 0) {
            if (t0 >= lengths[bb]) return;                  // fwd uses G[t < L]
        } else {
            const int q4 = bb & ~3;
            int mx = lengths[q4];
            mx = max(mx, lengths[q4 + 1]);
            mx = max(mx, lengths[q4 + 2]);
            mx = max(mx, lengths[q4 + 3]);
            if (t0 >= mx) return;                           // bwd uses G[t < maxL4]
        }
    }

    const float* w  = dir ? wb  : wf;
    const float* bi = dir ? bib : bif;
    const float* bh = dir ? bhb : bhf;

    const int tid = threadIdx.x;
    const int bN = blockIdx.y * 64;
    const int ty = tid >> 4;
    const int tx = tid & 15;

    unsigned long long acc[8][2];
#pragma unroll
    for (int i = 0; i < 8; ++i) { acc[i][0] = 0ull; acc[i][1] = 0ull; }

    const int rowL = tid >> 3;
    const int kL   = (tid & 7) << 2;
    const float* xg = x + (size_t)(bM + rowL) * DD + kL;
    const float* wg = w + (size_t)(bN + rowL) * DD + kL;

    const uint32_t sAa = cvta_s(sA) + ty * 32;
    const uint32_t sBa = cvta_s(sB) + tx * 16;

    for (int kt = 0; kt < 8; ++kt) {
        const int k0 = kt * 32;
#pragma unroll
        for (int p = 0; p < 4; ++p) {
            float4 v = *(const float4*)(xg + (size_t)p * 32 * DD + k0);
            int m = rowL + p * 32;
            sA[(kL + 0) * 132 + m] = v.x;
            sA[(kL + 1) * 132 + m] = v.y;
            sA[(kL + 2) * 132 + m] = v.z;
            sA[(kL + 3) * 132 + m] = v.w;
        }
#pragma unroll
        for (int p = 0; p < 2; ++p) {
            float4 v = *(const float4*)(wg + (size_t)p * 32 * DD + k0);
            int n = rowL + p * 32;
            sB[(kL + 0) * 68 + n] = v.x;
            sB[(kL + 1) * 68 + n] = v.y;
            sB[(kL + 2) * 68 + n] = v.z;
            sB[(kL + 3) * 68 + n] = v.w;
        }
        __syncthreads();
#pragma unroll
        for (int kk = 0; kk < 32; ++kk) {
            float a0, a1, a2, a3, a4, a5, a6, a7;
            LDS_V4F32(a0, a1, a2, a3, sAa + kk * 528);
            LDS_V4F32(a4, a5, a6, a7, sAa + kk * 528 + 16);
            unsigned long long b01, b23;
            LDS_V2U64(b01, b23, sBa + kk * 272);
            unsigned long long aa;
            PACK2(aa, a0); FMA2(acc[0][0], aa, b01); FMA2(acc[0][1], aa, b23);
            PACK2(aa, a1); FMA2(acc[1][0], aa, b01); FMA2(acc[1][1], aa, b23);
            PACK2(aa, a2); FMA2(acc[2][0], aa, b01); FMA2(acc[2][1], aa, b23);
            PACK2(aa, a3); FMA2(acc[3][0], aa, b01); FMA2(acc[3][1], aa, b23);
            PACK2(aa, a4); FMA2(acc[4][0], aa, b01); FMA2(acc[4][1], aa, b23);
            PACK2(aa, a5); FMA2(acc[5][0], aa, b01); FMA2(acc[5][1], aa, b23);
            PACK2(aa, a6); FMA2(acc[6][0], aa, b01); FMA2(acc[6][1], aa, b23);
            PACK2(aa, a7); FMA2(acc[7][0], aa, b01); FMA2(acc[7][1], aa, b23);
        }
        __syncthreads();
    }

    float bias[4];
#pragma unroll
    for (int c = 0; c < 4; ++c) {
        int j = bN + tx * 4 + c;
        bias[c] = bi[j] + bh[j];
    }
    float* Gd = g_G + (size_t)dir * BB * TT * G4;
#pragma unroll
    for (int i = 0; i < 8; ++i) {
        int m = bM + ty * 8 + i;
        float c0, c1, c2, c3;
        UNPACK2(c0, c1, acc[i][0]);
        UNPACK2(c2, c3, acc[i][1]);
        float4 o = make_float4(c0 + bias[0], c1 + bias[1], c2 + bias[2], c3 + bias[3]);
        *(float4*)(Gd + (size_t)m * G4 + bN + tx * 4) = o;
    }
}

// ---------------- noop (shifts ncu capture index so rec gets profiled) ----------------
__global__ void noop_kernel() {}

// ---------------- Kernel 2: LSTM recurrence — warp-autonomous steps ----------
// 16 clusters of 8 CTAs. CTA rank r owns units [32r,32r+32). 256 threads, 8 warps.
// Warp w owns units r*32 + w*4 + ul, ul∈[0,4). Lane = ul*8 + gate*2 + kh.
// Row = gate*32 + w*4 + ul; weights (k-half kh) in 64 regs as packed f32x2 pairs.
// k-reduce via shfl.xor(1) (bit-identical to R8 order). Gate transpose through a
// warp-private smem slice (__syncwarp only). Act in ALL warps (kh-redundant);
// each lane issues 2 paired-b64 st.async. NO __syncthreads in the loop.
// Exchange protocol identical to R8: tx-counted ping-pong mbarriers, tx=4096.
// Steps capped at maxL4 (outputs beyond each batch's L are mask-discarded).
#define REC_SMEM_BYTES  12304   // h 8192 | transpose 4096 | pad
#define RECV_BYTES      4096u

__global__ void __launch_bounds__(256, 1) __cluster_dims__(8, 1, 1)
lstm_rec_kernel(const float* __restrict__ whh_f, const float* __restrict__ whh_b,
                const int* __restrict__ lengths)
{
    extern __shared__ float sm[];
    __shared__ __align__(8) unsigned long long s_bar[2];

    cg::cluster_group cluster = cg::this_cluster();
    const int rank = cluster.block_rank();
    const int cidx = blockIdx.x >> 3;
    const int dir  = cidx >> 3;
    const int b0   = (cidx & 7) * 4;
    const int tid  = threadIdx.x;
    const int w_   = tid >> 5;          // warp 0..7
    const int lane = tid & 31;
    const int ul   = lane >> 3;         // unit-local 0..3
    const int gate = (lane >> 1) & 3;   // gate 0..3 (also acts as batch index)
    const int kh   = lane & 1;          // k half

    const float* whh = dir ? whh_b : whh_f;

    const int unit  = (rank << 5) + (w_ << 2) + ul;       // global hidden unit
    const int row_g = (gate << 8) + (rank << 5) + (w_ << 2) + ul;   // global gate row

    // weights: this lane's k-half of its row, 128 floats as 64 packed pairs
    ulonglong2 wreg[32];
    {
        const ulonglong2* wrow = (const ulonglong2*)(whh + (size_t)row_g * HH + kh * 128);
#pragma unroll
        for (int j = 0; j < 32; ++j) wreg[j] = wrow[j];
    }

    for (int i = tid; i < 2048; i += 256) sm[i] = 0.0f;   // both h buffers

    const uint32_t bar0 = cvta_s(&s_bar[0]);
    const uint32_t bar1 = cvta_s(&s_bar[1]);
    if (tid == 0) {
        MBAR_INIT(bar0, 1);
        MBAR_INIT(bar1, 1);
    }
    __syncthreads();
    cluster.sync();
    if (tid == 0) {
        MBAR_ARRIVE_EXPECT(bar0, RECV_BYTES);
        MBAR_ARRIVE_EXPECT(bar1, RECV_BYTES);
    }

    int L[4];
#pragma unroll
    for (int b = 0; b < 4; ++b) L[b] = lengths[b0 + b];
    int maxL = max(max(L[0], L[1]), max(L[2], L[3]));

    const uint32_t sh_u32 = cvta_s(sm);

    // this lane's 2 send destinations: ranks {r0, r0+1}, r0 = kh*4 + (ul&1)*2
    const int r0 = kh * 4 + (ul & 1) * 2;
    uint32_t remh0, remh1, rb0a, rb0b, rb1a, rb1b;
    MAPA(remh0, sh_u32, r0);     MAPA(remh1, sh_u32, r0 + 1);
    MAPA(rb0a, bar0, r0);        MAPA(rb0b, bar0, r0 + 1);
    MAPA(rb1a, bar1, r0);        MAPA(rb1b, bar1, r0 + 1);

    const int beta = gate;               // batch handled by this lane's act
    const int Lb   = L[beta];
    float c_state = 0.0f;

    const float* Gbase = g_G + (size_t)dir * BB * TT * G4;
    float* hbase = g_h + (size_t)dir * BB * TT * HH;

    // warp-private transpose slice: [w][kh][ul][gate][4b] floats
    const uint32_t tb = sh_u32 + 8192 + (((w_ * 2 + kh) * 4 + ul) * 16) * 4;

    const int LA = L[0], LB = L[1], LC = L[2], LD = L[3];

    uint32_t ph0 = 0, ph1 = 0;
    int cur = 0;
    for (int s = 0; s < maxL; ++s) {
        const int nxt = cur ^ 1;
        float p0, p1, p2, p3;
        if (kh == 0) {   // G prefetch for this row, all 4 batches (before the wait)
            int tA = dir ? (s < LA ? LA - 1 - s : s) : s;
            int tB = dir ? (s < LB ? LB - 1 - s : s) : s;
            int tC = dir ? (s < LC ? LC - 1 - s : s) : s;
            int tD = dir ? (s < LD ? LD - 1 - s : s) : s;
            p0 = Gbase[((size_t)(b0 + 0) * TT + tA) * G4 + row_g];
            p1 = Gbase[((size_t)(b0 + 1) * TT + tB) * G4 + row_g];
            p2 = Gbase[((size_t)(b0 + 2) * TT + tC) * G4 + row_g];
            p3 = Gbase[((size_t)(b0 + 3) * TT + tD) * G4 + row_g];
        }

        if (s > 0) {
            if (s & 1) { mbar_wait(bar1, ph1); ph1 ^= 1; if (tid == 0) MBAR_ARRIVE_EXPECT(bar1, RECV_BYTES); }
            else       { mbar_wait(bar0, ph0); ph0 ^= 1; if (tid == 0) MBAR_ARRIVE_EXPECT(bar0, RECV_BYTES); }
        }

        // matvec: this lane's k-half of its row, 4 batches; h [buf][b][256 k]
        unsigned long long aE0 = 0ull, aO0 = 0ull, aE1 = 0ull, aO1 = 0ull;
        unsigned long long aE2 = 0ull, aO2 = 0ull, aE3 = 0ull, aO3 = 0ull;
        const uint32_t hb0 = sh_u32 + (cur << 12) + kh * 512;
#pragma unroll
        for (int j = 0; j < 32; ++j) {
            unsigned long long x0, y0, x1, y1, x2, y2, x3, y3;
            LDS_V2U64(x0, y0, hb0 + j * 16);
            LDS_V2U64(x1, y1, hb0 + 1024 + j * 16);
            LDS_V2U64(x2, y2, hb0 + 2048 + j * 16);
            LDS_V2U64(x3, y3, hb0 + 3072 + j * 16);
            FMA2(aE0, wreg[j].x, x0); FMA2(aO0, wreg[j].y, y0);
            FMA2(aE1, wreg[j].x, x1); FMA2(aO1, wreg[j].y, y1);
            FMA2(aE2, wreg[j].x, x2); FMA2(aO2, wreg[j].y, y2);
            FMA2(aE3, wreg[j].x, x3); FMA2(aO3, wreg[j].y, y3);
        }
        unsigned long long q0, q1, q2, q3;
        ADD2(q0, aE0, aO0); ADD2(q1, aE1, aO1);
        ADD2(q2, aE2, aO2); ADD2(q3, aE3, aO3);
        float e, o, s0, s1, s2, s3;
        UNPACK2(e, o, q0); s0 = e + o;
        UNPACK2(e, o, q1); s1 = e + o;
        UNPACK2(e, o, q2); s2 = e + o;
        UNPACK2(e, o, q3); s3 = e + o;
        if (kh == 0) { s0 += p0; s1 += p1; s2 += p2; s3 += p3; }
        // k-half reduce: lanes L <-> L^1 (kh flip). kh0 holds (dot0+G), adds dot1.
        s0 += __shfl_xor_sync(0xffffffffu, s0, 1);
        s1 += __shfl_xor_sync(0xffffffffu, s1, 1);
        s2 += __shfl_xor_sync(0xffffffffu, s2, 1);
        s3 += __shfl_xor_sync(0xffffffffu, s3, 1);

        // gate transpose through warp-private smem (no CTA sync)
        asm volatile("st.shared.v4.f32 [%0], {%1, %2, %3, %4};"
                     :: "r"(tb + gate * 16), "f"(s0), "f"(s1), "f"(s2), "f"(s3) : "memory");
        __syncwarp();
        float iv, fv, gv, ov;
        asm volatile("ld.shared.f32 %0, [%1];" : "=f"(iv) : "r"(tb +  0 + beta * 4));
        asm volatile("ld.shared.f32 %0, [%1];" : "=f"(fv) : "r"(tb + 16 + beta * 4));
        asm volatile("ld.shared.f32 %0, [%1];" : "=f"(gv) : "r"(tb + 32 + beta * 4));
        asm volatile("ld.shared.f32 %0, [%1];" : "=f"(ov) : "r"(tb + 48 + beta * 4));
        __syncwarp();

        // act for (unit, batch beta) — kh-redundant, bit-identical in both lanes
        float c_new = sigf(fv) * c_state + sigf(iv) * tanhf2(gv);
        float h_new = sigf(ov) * tanhf2(c_new);
        c_state = c_new;

        if (kh == 0) {   // one store per (unit, beta)
            int tt = dir ? (s < Lb ? Lb - 1 - s : s) : s;
            hbase[((size_t)(b0 + beta) * TT + tt) * HH + unit] = h_new;
        }

        // pair adjacent units (ul bit0 = lane bit3) and send b64 to 2 ranks
        float hp = __shfl_xor_sync(0xffffffffu, h_new, 8);
        unsigned long long pkt;
        if (ul & 1) { PACKP(pkt, hp, h_new); } else { PACKP(pkt, h_new, hp); }
        const uint32_t off = (((nxt * 4 + beta) << 8) + (unit & ~1)) * 4;
        if ((s + 1) & 1) {
            ST_ASYNC_B64(remh0 + off, pkt, rb1a);
            ST_ASYNC_B64(remh1 + off, pkt, rb1b);
        } else {
            ST_ASYNC_B64(remh0 + off, pkt, rb0a);
            ST_ASYNC_B64(remh1 + off, pkt, rb0b);
        }
        cur = nxt;
    }
    cluster.sync();   // protect in-flight final sends before exit
}

// ---------------- Kernel 3: emissions ----------------
__global__ void __launch_bounds__(256) emis_kernel(const float* __restrict__ wtag,
                                                   const float* __restrict__ btag)
{
    __shared__ float sw[KK * 512];
    __shared__ float sb[KK];
    for (int i = threadIdx.x; i < KK * 512; i += 256) sw[i] = wtag[i];
    if (threadIdx.x < KK) sb[threadIdx.x] = btag[threadIdx.x];
    __syncthreads();

    const int warp = threadIdx.x >> 5, lane = threadIdx.x & 31;
    const size_t m = (size_t)blockIdx.x * 8 + warp;
    const float* hf = g_h + m * HH;
    const float* hb = g_h + (size_t)BB * TT * HH + m * HH;

    float acc[KK];
#pragma unroll
    for (int k = 0; k < KK; ++k) acc[k] = 0.0f;
#pragma unroll
    for (int i = 0; i < 8; ++i) {
        int idx = lane + i * 32;
        float a = hf[idx], b2 = hb[idx];
#pragma unroll
        for (int k = 0; k < KK; ++k) {
            acc[k] = fmaf(a,  sw[k * 512 + idx],       acc[k]);
            acc[k] = fmaf(b2, sw[k * 512 + 256 + idx], acc[k]);
        }
    }
#pragma unroll
    for (int k = 0; k < KK; ++k) {
        float v = acc[k];
#pragma unroll
        for (int off = 16; off; off >>= 1) v += __shfl_xor_sync(~0u, v, off);
        if (lane == 0) g_emis[m * KK + k] = v + sb[k];
    }
}

// ---------------- Kernel 4: CRF (4-deep E prefetch; max-free lse) ----------------
__global__ void crf_kernel(const int* __restrict__ tags, const int* __restrict__ lengths,
                           const float* __restrict__ start_trans,
                           const float* __restrict__ end_trans,
                           const float* __restrict__ trans)
{
    const int b = blockIdx.x;
    const int lane = threadIdx.x & 31;
    const int L = lengths[b];
    const float* E = g_emis + (size_t)b * TT * KK;
    const int* tg = tags + (size_t)b * TT;
    const int j  = lane & 7;
    const int i0 = (lane >> 3) * 2;
    const int i1 = i0 + 1;

    const float tc0 = trans[i0 * KK + j];
    const float tc1 = trans[i1 * KK + j];

    float sc = start_trans[j] + E[j];
    float e1 = E[1 * KK + j], e2 = E[2 * KK + j], e3 = E[3 * KK + j], e4 = E[4 * KK + j];
#pragma unroll 4
    for (int t = 1; t < TT; ++t) {
        float e = e1; e1 = e2; e2 = e3; e3 = e4;
        if (t + 4 < TT) e4 = E[(t + 4) * KK + j];
        float s0 = __shfl_sync(~0u, sc, i0) + tc0;
        float s1 = __shfl_sync(~0u, sc, i1) + tc1;
        float pv = __expf(s0 - sc) + __expf(s1 - sc);
        pv += __shfl_xor_sync(~0u, pv, 8);
        pv += __shfl_xor_sync(~0u, pv, 16);
        float nxt = sc + __logf(pv) + e;
        sc = (t < L) ? nxt : sc;
    }

    float z = sc + end_trans[j];
    float mz = z;
#pragma unroll
    for (int off = 4; off; off >>= 1) mz = fmaxf(mz, __shfl_xor_sync(~0u, mz, off));
    float sz = __expf(z - mz);
#pragma unroll
    for (int off = 4; off; off >>= 1) sz += __shfl_xor_sync(~0u, sz, off);
    float logZ = mz + __logf(sz);

    float part = 0.0f;
    for (int t = 1 + lane; t < TT; t += 32)
        if (t < L) part += trans[tg[t - 1] * KK + tg[t]] + E[t * KK + tg[t]];
#pragma unroll
    for (int off = 16; off; off >>= 1) part += __shfl_xor_sync(~0u, part, off);

    if (lane == 0) {
        int t0 = tg[0];
        float num = start_trans[t0] + E[t0] + part + end_trans[tg[L - 1]];
        g_res[b] = num - logZ;
    }
}

// ---------------- Kernel 5: finalize ----------------
__global__ void finalize_kernel(float* __restrict__ out)
{
    float v = g_res[threadIdx.x];
#pragma unroll
    for (int off = 16; off; off >>= 1) v += __shfl_xor_sync(~0u, v, off);
    if (threadIdx.x == 0) out[0] = -v / (float)BB;
}

// ---------------- launch ----------------
extern "C" void kernel_launch(void* const* d_in, const int* in_sizes, int n_in,
                              void* d_out, int out_size)
{
    const float* sentences = (const float*)d_in[0];
    const int*   tags      = (const int*)  d_in[1];
    const int*   lengths   = (const int*)  d_in[2];
    const float* w_ih_f = (const float*)d_in[4];
    const float* w_hh_f = (const float*)d_in[5];
    const float* b_ih_f = (const float*)d_in[6];
    const float* b_hh_f = (const float*)d_in[7];
    const float* w_ih_b = (const float*)d_in[8];
    const float* w_hh_b = (const float*)d_in[9];
    const float* b_ih_b = (const float*)d_in[10];
    const float* b_hh_b = (const float*)d_in[11];
    const float* w_tag  = (const float*)d_in[12];
    const float* b_tag  = (const float*)d_in[13];
    const float* start_trans = (const float*)d_in[14];
    const float* end_trans   = (const float*)d_in[15];
    const float* trans       = (const float*)d_in[16];
    float* out = (float*)d_out;

    dim3 pg(512, 16, 2);
    proj_kernel<<<pg, 256>>>(sentences, w_ih_f, b_ih_f, b_hh_f,
                             w_ih_b, b_ih_b, b_hh_b, lengths);
    noop_kernel<<<1, 32>>>();
    noop_kernel<<<1, 32>>>();
    lstm_rec_kernel<<<128, 256, REC_SMEM_BYTES>>>(w_hh_f, w_hh_b, lengths);
    emis_kernel<<<(BB * TT) / 8, 256>>>(w_tag, b_tag);
    crf_kernel<<<BB, 32>>>(tags, lengths, start_trans, end_trans, trans);
    finalize_kernel<<<1, 32>>>(out);
}

// round 16
// speedup vs baseline: 1.0511x; 1.0511x over previous
#include <cuda_runtime.h>
#include <cuda_bf16.h>
#include <cooperative_groups.h>
#include <cstdint>

namespace cg = cooperative_groups;

#define BB 32
#define TT 2048
#define DD 256
#define HH 256
#define G4 1024
#define KK 8

__device__ float g_G[(size_t)2 * BB * TT * G4];
__device__ float g_h[(size_t)2 * BB * TT * HH];
__device__ float g_emis[(size_t)BB * TT * KK];
__device__ float g_res[BB];

__device__ __forceinline__ uint32_t cvta_s(const void* p) {
    return (uint32_t)__cvta_generic_to_shared(p);
}

#define FMA2(acc, a, b) asm("fma.rn.f32x2 %0, %1, %2, %0;" : "+l"(acc) : "l"(a), "l"(b))
#define ADD2(d, a, b)   asm("add.rn.f32x2 %0, %1, %2;" : "=l"(d) : "l"(a), "l"(b))
#define PACK2(d, s)     asm("mov.b64 %0, {%1, %1};" : "=l"(d) : "f"(s))
#define PACKP(d, lo, hi) asm("mov.b64 %0, {%1, %2};" : "=l"(d) : "f"(lo), "f"(hi))
#define UNPACK2(lo, hi, v) asm("mov.b64 {%0, %1}, %2;" : "=f"(lo), "=f"(hi) : "l"(v))
#define LDS_V2U64(a, b, addr) \
    asm("ld.shared.v2.b64 {%0, %1}, [%2];" : "=l"(a), "=l"(b) : "r"(addr))
#define LDS_V4F32(w0, w1, w2, w3, addr) \
    asm("ld.shared.v4.f32 {%0, %1, %2, %3}, [%4];" \
        : "=f"(w0), "=f"(w1), "=f"(w2), "=f"(w3) : "r"(addr))

#define MBAR_INIT(addr, cnt) \
    asm volatile("mbarrier.init.shared.b64 [%0], %1;" :: "r"(addr), "r"(cnt) : "memory")
#define MBAR_ARRIVE_EXPECT(addr, bytes) \
    asm volatile("mbarrier.arrive.expect_tx.shared.b64 _, [%0], %1;" \
                 :: "r"(addr), "r"(bytes) : "memory")
#define ST_ASYNC_B32(raddr, val, rmbar) \
    asm volatile("st.async.shared::cluster.mbarrier::complete_tx::bytes.b32 [%0], %1, [%2];" \
                 :: "r"(raddr), "f"(val), "r"(rmbar) : "memory")
#define MAPA(dst, laddr, rank) \
    asm("mapa.shared::cluster.u32 %0, %1, %2;" : "=r"(dst) : "r"(laddr), "r"(rank))

__device__ __forceinline__ void mbar_wait(uint32_t mbar, uint32_t parity) {
    uint32_t done;
    asm volatile(
        "{\n\t.reg .pred p;\n\t"
        "mbarrier.try_wait.parity.acquire.cta.shared::cta.b64 p, [%1], %2;\n\t"
        "selp.b32 %0, 1, 0, p;\n\t}"
        : "=r"(done) : "r"(mbar), "r"(parity) : "memory");
    if (!done) {
        asm volatile(
            "{\n\t.reg .pred P1;\n\t"
            "WL_%=:\n\t"
            "mbarrier.try_wait.parity.acquire.cta.shared::cta.b64 P1, [%0], %1, 0x989680;\n\t"
            "@P1 bra.uni WD_%=;\n\t"
            "bra.uni WL_%=;\n\t"
            "WD_%=:\n\t}"
            :: "r"(mbar), "r"(parity) : "memory");
    }
}

__device__ __forceinline__ float sigf(float x)   { return 1.0f / (1.0f + __expf(-x)); }
__device__ __forceinline__ float tanhf2(float x) { return 2.0f / (1.0f + __expf(-2.0f * x)) - 1.0f; }

// ---------------- Kernel 1: input projection GEMM (f32x2) + tile elision ----------------
__global__ void __launch_bounds__(256, 3) proj_kernel(
    const float* __restrict__ x,
    const float* __restrict__ wf, const float* __restrict__ bif, const float* __restrict__ bhf,
    const float* __restrict__ wb, const float* __restrict__ bib, const float* __restrict__ bhb,
    const int* __restrict__ lengths)
{
    __shared__ float sA[32 * 132];
    __shared__ float sB[32 * 68];

    const int dir = blockIdx.z;
    const int bM = blockIdx.x * 128;

    {   // elision: G beyond these t are only consumed at mask-discarded positions
        const int bb = bM >> 11;
        const int t0 = bM & 2047;
        if (dir == 0) {
            if (t0 >= lengths[bb]) return;
        } else {
            const int q4 = bb & ~3;
            int mx = lengths[q4];
            mx = max(mx, lengths[q4 + 1]);
            mx = max(mx, lengths[q4 + 2]);
            mx = max(mx, lengths[q4 + 3]);
            if (t0 >= mx) return;
        }
    }

    const float* w  = dir ? wb  : wf;
    const float* bi = dir ? bib : bif;
    const float* bh = dir ? bhb : bhf;

    const int tid = threadIdx.x;
    const int bN = blockIdx.y * 64;
    const int ty = tid >> 4;
    const int tx = tid & 15;

    unsigned long long acc[8][2];
#pragma unroll
    for (int i = 0; i < 8; ++i) { acc[i][0] = 0ull; acc[i][1] = 0ull; }

    const int rowL = tid >> 3;
    const int kL   = (tid & 7) << 2;
    const float* xg = x + (size_t)(bM + rowL) * DD + kL;
    const float* wg = w + (size_t)(bN + rowL) * DD + kL;

    const uint32_t sAa = cvta_s(sA) + ty * 32;
    const uint32_t sBa = cvta_s(sB) + tx * 16;

    for (int kt = 0; kt < 8; ++kt) {
        const int k0 = kt * 32;
#pragma unroll
        for (int p = 0; p < 4; ++p) {
            float4 v = *(const float4*)(xg + (size_t)p * 32 * DD + k0);
            int m = rowL + p * 32;
            sA[(kL + 0) * 132 + m] = v.x;
            sA[(kL + 1) * 132 + m] = v.y;
            sA[(kL + 2) * 132 + m] = v.z;
            sA[(kL + 3) * 132 + m] = v.w;
        }
#pragma unroll
        for (int p = 0; p < 2; ++p) {
            float4 v = *(const float4*)(wg + (size_t)p * 32 * DD + k0);
            int n = rowL + p * 32;
            sB[(kL + 0) * 68 + n] = v.x;
            sB[(kL + 1) * 68 + n] = v.y;
            sB[(kL + 2) * 68 + n] = v.z;
            sB[(kL + 3) * 68 + n] = v.w;
        }
        __syncthreads();
#pragma unroll
        for (int kk = 0; kk < 32; ++kk) {
            float a0, a1, a2, a3, a4, a5, a6, a7;
            LDS_V4F32(a0, a1, a2, a3, sAa + kk * 528);
            LDS_V4F32(a4, a5, a6, a7, sAa + kk * 528 + 16);
            unsigned long long b01, b23;
            LDS_V2U64(b01, b23, sBa + kk * 272);
            unsigned long long aa;
            PACK2(aa, a0); FMA2(acc[0][0], aa, b01); FMA2(acc[0][1], aa, b23);
            PACK2(aa, a1); FMA2(acc[1][0], aa, b01); FMA2(acc[1][1], aa, b23);
            PACK2(aa, a2); FMA2(acc[2][0], aa, b01); FMA2(acc[2][1], aa, b23);
            PACK2(aa, a3); FMA2(acc[3][0], aa, b01); FMA2(acc[3][1], aa, b23);
            PACK2(aa, a4); FMA2(acc[4][0], aa, b01); FMA2(acc[4][1], aa, b23);
            PACK2(aa, a5); FMA2(acc[5][0], aa, b01); FMA2(acc[5][1], aa, b23);
            PACK2(aa, a6); FMA2(acc[6][0], aa, b01); FMA2(acc[6][1], aa, b23);
            PACK2(aa, a7); FMA2(acc[7][0], aa, b01); FMA2(acc[7][1], aa, b23);
        }
        __syncthreads();
    }

    float bias[4];
#pragma unroll
    for (int c = 0; c < 4; ++c) {
        int j = bN + tx * 4 + c;
        bias[c] = bi[j] + bh[j];
    }
    float* Gd = g_G + (size_t)dir * BB * TT * G4;
#pragma unroll
    for (int i = 0; i < 8; ++i) {
        int m = bM + ty * 8 + i;
        float c0, c1, c2, c3;
        UNPACK2(c0, c1, acc[i][0]);
        UNPACK2(c2, c3, acc[i][1]);
        float4 o = make_float4(c0 + bias[0], c1 + bias[1], c2 + bias[2], c3 + bias[3]);
        *(float4*)(Gd + (size_t)m * G4 + bN + tx * 4) = o;
    }
}

// ---------------- noop (shifts ncu capture index so rec gets profiled) ----------------
__global__ void noop_kernel() {}

// ---------------- Kernel 2: LSTM recurrence — VERBATIM R5 (best: 8524 us) ----------
#define REC_SMEM_FLOATS (2048 + 1024)
#define REC_SMEM_BYTES  (REC_SMEM_FLOATS * 4)
#define RECV_BYTES      4096u   // 8 ranks * 128 values * 4 B per step

__global__ void __launch_bounds__(256, 1) __cluster_dims__(8, 1, 1)
lstm_rec_kernel(const float* __restrict__ whh_f, const float* __restrict__ whh_b,
                const int* __restrict__ lengths)
{
    extern __shared__ float sm[];
    float* s_h    = sm;            // [2 buf][256 k][4 b]
    float* s_part = sm + 2048;     // [2 kh][128 g][4 b]
    __shared__ __align__(8) unsigned long long s_bar[2];

    cg::cluster_group cluster = cg::this_cluster();
    const int rank = cluster.block_rank();
    const int cidx = blockIdx.x >> 3;
    const int dir  = cidx >> 3;
    const int b0   = (cidx & 7) * 4;
    const int tid  = threadIdx.x;
    const int kh   = tid >> 7;
    const int g    = tid & 127;

    const float* whh = dir ? whh_b : whh_f;

    const int gt = g >> 5, ul = g & 31;
    const int row_g = (gt << 8) + (rank << 5) + ul;

    float4 wreg[32];
    {
        const float4* wrow = (const float4*)(whh + (size_t)row_g * HH + kh * 128);
#pragma unroll
        for (int j = 0; j < 32; ++j) wreg[j] = wrow[j];
    }

    for (int i = tid; i < 2048; i += 256) s_h[i] = 0.0f;

    const uint32_t bar0 = cvta_s(&s_bar[0]);
    const uint32_t bar1 = cvta_s(&s_bar[1]);
    if (tid == 0) {
        MBAR_INIT(bar0, 1);
        MBAR_INIT(bar1, 1);
    }
    __syncthreads();
    cluster.sync();
    if (tid == 0) {
        MBAR_ARRIVE_EXPECT(bar0, RECV_BYTES);
        MBAR_ARRIVE_EXPECT(bar1, RECV_BYTES);
    }

    int L[4];
#pragma unroll
    for (int b = 0; b < 4; ++b) L[b] = lengths[b0 + b];

    const uint32_t sh_u32 = cvta_s(s_h);
    uint32_t rem_h[8], rem_b0[8], rem_b1[8];
#pragma unroll
    for (int r = 0; r < 8; ++r) {
        MAPA(rem_h[r], sh_u32, r);
        MAPA(rem_b0[r], bar0, r);
        MAPA(rem_b1[r], bar1, r);
    }

    const int t2  = g;
    const int ul2 = t2 >> 2, bu = t2 & 3;
    const int ugl = (rank << 5) + ul2;
    const int Lu  = L[bu];
    float c_state = 0.0f;

    const int LA = L[0], LB = L[1], LC = L[2], LD = L[3];

    const float* Gbase = g_G + (size_t)dir * BB * TT * G4;
    float* hbase = g_h + (size_t)dir * BB * TT * HH;

    const uint32_t part_a = cvta_s(s_part) + (kh * 128 + g) * 16;

    uint32_t ph0 = 0, ph1 = 0;
    int cur = 0;
    for (int s = 0; s < TT; ++s) {
        float p0, p1, p2, p3;
        if (kh == 0) {
            int tA = dir ? (s < LA ? LA - 1 - s : s) : s;
            int tB = dir ? (s < LB ? LB - 1 - s : s) : s;
            int tC = dir ? (s < LC ? LC - 1 - s : s) : s;
            int tD = dir ? (s < LD ? LD - 1 - s : s) : s;
            p0 = Gbase[((size_t)(b0 + 0) * TT + tA) * G4 + row_g];
            p1 = Gbase[((size_t)(b0 + 1) * TT + tB) * G4 + row_g];
            p2 = Gbase[((size_t)(b0 + 2) * TT + tC) * G4 + row_g];
            p3 = Gbase[((size_t)(b0 + 3) * TT + tD) * G4 + row_g];
        }

        if (s > 0) {
            if (s & 1) { mbar_wait(bar1, ph1); ph1 ^= 1; if (tid == 0) MBAR_ARRIVE_EXPECT(bar1, RECV_BYTES); }
            else       { mbar_wait(bar0, ph0); ph0 ^= 1; if (tid == 0) MBAR_ARRIVE_EXPECT(bar0, RECV_BYTES); }
        }

        unsigned long long a01e = 0ull, a23e = 0ull, a01o = 0ull, a23o = 0ull;
        uint32_t ha = sh_u32 + (cur << 12) + kh * 2048;
#pragma unroll
        for (int j = 0; j < 32; ++j) {
            float4 wv = wreg[j];
            unsigned long long h01, h23, wd;
            LDS_V2U64(h01, h23, ha);
            PACK2(wd, wv.x); FMA2(a01e, wd, h01); FMA2(a23e, wd, h23);
            LDS_V2U64(h01, h23, ha + 16);
            PACK2(wd, wv.y); FMA2(a01o, wd, h01); FMA2(a23o, wd, h23);
            LDS_V2U64(h01, h23, ha + 32);
            PACK2(wd, wv.z); FMA2(a01e, wd, h01); FMA2(a23e, wd, h23);
            LDS_V2U64(h01, h23, ha + 48);
            PACK2(wd, wv.w); FMA2(a01o, wd, h01); FMA2(a23o, wd, h23);
            ha += 64;
        }
        unsigned long long a01, a23;
        ADD2(a01, a01e, a01o);
        ADD2(a23, a23e, a23o);
        if (kh == 0) {
            unsigned long long gp;
            PACKP(gp, p0, p1); ADD2(a01, a01, gp);
            PACKP(gp, p2, p3); ADD2(a23, a23, gp);
        }
        asm volatile("st.shared.v2.b64 [%0], {%1, %2};" :: "r"(part_a), "l"(a01), "l"(a23) : "memory");
        __syncthreads();

        if (kh == 1) {
            float iv = s_part[(0   + ul2) * 4 + bu] + s_part[512 + (0   + ul2) * 4 + bu];
            float fv = s_part[(32  + ul2) * 4 + bu] + s_part[512 + (32  + ul2) * 4 + bu];
            float gv = s_part[(64  + ul2) * 4 + bu] + s_part[512 + (64  + ul2) * 4 + bu];
            float ov = s_part[(96  + ul2) * 4 + bu] + s_part[512 + (96  + ul2) * 4 + bu];
            float c_new = sigf(fv) * c_state + sigf(iv) * tanhf2(gv);
            float h_new = sigf(ov) * tanhf2(c_new);
            c_state = c_new;

            const int nxt = cur ^ 1;
            const uint32_t off = ((nxt << 10) + (ugl << 2) + bu) * 4;
            const int sb = (s + 1) & 1;
#pragma unroll
            for (int r = 0; r < 8; ++r)
                ST_ASYNC_B32(rem_h[r] + off, h_new, sb ? rem_b1[r] : rem_b0[r]);

            int tt = dir ? (s < Lu ? Lu - 1 - s : s) : s;
            hbase[((size_t)(b0 + bu) * TT + tt) * HH + ugl] = h_new;
        }
        cur ^= 1;
    }
    cluster.sync();
}

// ---------------- Kernel 3: emissions (skip t >= L_b) ----------------
__global__ void __launch_bounds__(256) emis_kernel(const float* __restrict__ wtag,
                                                   const float* __restrict__ btag,
                                                   const int* __restrict__ lengths)
{
    __shared__ float sw[KK * 512];
    __shared__ float sb[KK];
    for (int i = threadIdx.x; i < KK * 512; i += 256) sw[i] = wtag[i];
    if (threadIdx.x < KK) sb[threadIdx.x] = btag[threadIdx.x];
    __syncthreads();

    const int warp = threadIdx.x >> 5, lane = threadIdx.x & 31;
    const size_t m = (size_t)blockIdx.x * 8 + warp;
    const int bb = (int)(m / TT);
    const int tt = (int)(m % TT);
    if (tt >= lengths[bb]) return;     // emis beyond L is never read by crf

    const float* hf = g_h + m * HH;
    const float* hb = g_h + (size_t)BB * TT * HH + m * HH;

    float acc[KK];
#pragma unroll
    for (int k = 0; k < KK; ++k) acc[k] = 0.0f;
#pragma unroll
    for (int i = 0; i < 8; ++i) {
        int idx = lane + i * 32;
        float a = hf[idx], b2 = hb[idx];
#pragma unroll
        for (int k = 0; k < KK; ++k) {
            acc[k] = fmaf(a,  sw[k * 512 + idx],       acc[k]);
            acc[k] = fmaf(b2, sw[k * 512 + 256 + idx], acc[k]);
        }
    }
#pragma unroll
    for (int k = 0; k < KK; ++k) {
        float v = acc[k];
#pragma unroll
        for (int off = 16; off; off >>= 1) v += __shfl_xor_sync(~0u, v, off);
        if (lane == 0) g_emis[m * KK + k] = v + sb[k];
    }
}

// ---------------- Kernel 4: CRF (scan stops at L — identical math) ----------------
__global__ void crf_kernel(const int* __restrict__ tags, const int* __restrict__ lengths,
                           const float* __restrict__ start_trans,
                           const float* __restrict__ end_trans,
                           const float* __restrict__ trans)
{
    const int b = blockIdx.x;
    const int lane = threadIdx.x & 31;
    const int L = lengths[b];
    const float* E = g_emis + (size_t)b * TT * KK;
    const int* tg = tags + (size_t)b * TT;
    const int j  = lane & 7;
    const int i0 = (lane >> 3) * 2;
    const int i1 = i0 + 1;

    const float tc0 = trans[i0 * KK + j];
    const float tc1 = trans[i1 * KK + j];

    float sc = start_trans[j] + E[j];
    float e1 = E[1 * KK + j], e2 = E[2 * KK + j], e3 = E[3 * KK + j], e4 = E[4 * KK + j];
#pragma unroll 4
    for (int t = 1; t < L; ++t) {       // sc frozen for t >= L → loop to L only
        float e = e1; e1 = e2; e2 = e3; e3 = e4;
        if (t + 4 < TT) e4 = E[(t + 4) * KK + j];
        float s0 = __shfl_sync(~0u, sc, i0) + tc0;
        float s1 = __shfl_sync(~0u, sc, i1) + tc1;
        float pv = __expf(s0 - sc) + __expf(s1 - sc);
        pv += __shfl_xor_sync(~0u, pv, 8);
        pv += __shfl_xor_sync(~0u, pv, 16);
        sc = sc + __logf(pv) + e;
    }

    float z = sc + end_trans[j];
    float mz = z;
#pragma unroll
    for (int off = 4; off; off >>= 1) mz = fmaxf(mz, __shfl_xor_sync(~0u, mz, off));
    float sz = __expf(z - mz);
#pragma unroll
    for (int off = 4; off; off >>= 1) sz += __shfl_xor_sync(~0u, sz, off);
    float logZ = mz + __logf(sz);

    float part = 0.0f;
    for (int t = 1 + lane; t < L; t += 32)
        part += trans[tg[t - 1] * KK + tg[t]] + E[t * KK + tg[t]];
#pragma unroll
    for (int off = 16; off; off >>= 1) part += __shfl_xor_sync(~0u, part, off);

    if (lane == 0) {
        int t0 = tg[0];
        float num = start_trans[t0] + E[t0] + part + end_trans[tg[L - 1]];
        g_res[b] = num - logZ;
    }
}

// ---------------- Kernel 5: finalize ----------------
__global__ void finalize_kernel(float* __restrict__ out)
{
    float v = g_res[threadIdx.x];
#pragma unroll
    for (int off = 16; off; off >>= 1) v += __shfl_xor_sync(~0u, v, off);
    if (threadIdx.x == 0) out[0] = -v / (float)BB;
}

// ---------------- launch ----------------
extern "C" void kernel_launch(void* const* d_in, const int* in_sizes, int n_in,
                              void* d_out, int out_size)
{
    const float* sentences = (const float*)d_in[0];
    const int*   tags      = (const int*)  d_in[1];
    const int*   lengths   = (const int*)  d_in[2];
    const float* w_ih_f = (const float*)d_in[4];
    const float* w_hh_f = (const float*)d_in[5];
    const float* b_ih_f = (const float*)d_in[6];
    const float* b_hh_f = (const float*)d_in[7];
    const float* w_ih_b = (const float*)d_in[8];
    const float* w_hh_b = (const float*)d_in[9];
    const float* b_ih_b = (const float*)d_in[10];
    const float* b_hh_b = (const float*)d_in[11];
    const float* w_tag  = (const float*)d_in[12];
    const float* b_tag  = (const float*)d_in[13];
    const float* start_trans = (const float*)d_in[14];
    const float* end_trans   = (const float*)d_in[15];
    const float* trans       = (const float*)d_in[16];
    float* out = (float*)d_out;

    dim3 pg(512, 16, 2);
    proj_kernel<<<pg, 256>>>(sentences, w_ih_f, b_ih_f, b_hh_f,
                             w_ih_b, b_ih_b, b_hh_b, lengths);
    noop_kernel<<<1, 32>>>();
    noop_kernel<<<1, 32>>>();
    lstm_rec_kernel<<<128, 256, REC_SMEM_BYTES>>>(w_hh_f, w_hh_b, lengths);
    emis_kernel<<<(BB * TT) / 8, 256>>>(w_tag, b_tag, lengths);
    crf_kernel<<<BB, 32>>>(tags, lengths, start_trans, end_trans, trans);
    finalize_kernel<<<1, 32>>>(out);
}

// round 17
// speedup vs baseline: 1.6760x; 1.5945x over previous
#include <cuda_runtime.h>
#include <cuda_bf16.h>
#include <cooperative_groups.h>
#include <cstdint>

namespace cg = cooperative_groups;

#define BB 32
#define TT 2048
#define DD 256
#define HH 256
#define G4 1024
#define KK 8

__device__ float g_G[(size_t)2 * BB * TT * G4];
__device__ float g_h[(size_t)2 * BB * TT * HH];
__device__ float g_emis[(size_t)BB * TT * KK];
__device__ float g_res[BB];

__device__ __forceinline__ uint32_t cvta_s(const void* p) {
    return (uint32_t)__cvta_generic_to_shared(p);
}

#define FMA2(acc, a, b) asm("fma.rn.f32x2 %0, %1, %2, %0;" : "+l"(acc) : "l"(a), "l"(b))
#define ADD2(d, a, b)   asm("add.rn.f32x2 %0, %1, %2;" : "=l"(d) : "l"(a), "l"(b))
#define PACK2(d, s)     asm("mov.b64 %0, {%1, %1};" : "=l"(d) : "f"(s))
#define PACKP(d, lo, hi) asm("mov.b64 %0, {%1, %2};" : "=l"(d) : "f"(lo), "f"(hi))
#define UNPACK2(lo, hi, v) asm("mov.b64 {%0, %1}, %2;" : "=f"(lo), "=f"(hi) : "l"(v))
#define LDS_V2U64(a, b, addr) \
    asm("ld.shared.v2.b64 {%0, %1}, [%2];" : "=l"(a), "=l"(b) : "r"(addr))
#define LDS_V4F32(w0, w1, w2, w3, addr) \
    asm("ld.shared.v4.f32 {%0, %1, %2, %3}, [%4];" \
        : "=f"(w0), "=f"(w1), "=f"(w2), "=f"(w3) : "r"(addr))

#define MBAR_INIT(addr, cnt) \
    asm volatile("mbarrier.init.shared.b64 [%0], %1;" :: "r"(addr), "r"(cnt) : "memory")
#define MBAR_ARRIVE_EXPECT(addr, bytes) \
    asm volatile("mbarrier.arrive.expect_tx.shared.b64 _, [%0], %1;" \
                 :: "r"(addr), "r"(bytes) : "memory")
#define ST_ASYNC_B32(raddr, val, rmbar) \
    asm volatile("st.async.shared::cluster.mbarrier::complete_tx::bytes.b32 [%0], %1, [%2];" \
                 :: "r"(raddr), "f"(val), "r"(rmbar) : "memory")
#define MAPA(dst, laddr, rank) \
    asm("mapa.shared::cluster.u32 %0, %1, %2;" : "=r"(dst) : "r"(laddr), "r"(rank))

__device__ __forceinline__ void mbar_wait(uint32_t mbar, uint32_t parity) {
    uint32_t done;
    asm volatile(
        "{\n\t.reg .pred p;\n\t"
        "mbarrier.try_wait.parity.acquire.cta.shared::cta.b64 p, [%1], %2;\n\t"
        "selp.b32 %0, 1, 0, p;\n\t}"
        : "=r"(done) : "r"(mbar), "r"(parity) : "memory");
    if (!done) {
        asm volatile(
            "{\n\t.reg .pred P1;\n\t"
            "WL_%=:\n\t"
            "mbarrier.try_wait.parity.acquire.cta.shared::cta.b64 P1, [%0], %1, 0x989680;\n\t"
            "@P1 bra.uni WD_%=;\n\t"
            "bra.uni WL_%=;\n\t"
            "WD_%=:\n\t}"
            :: "r"(mbar), "r"(parity) : "memory");
    }
}

__device__ __forceinline__ float sigf(float x)   { return 1.0f / (1.0f + __expf(-x)); }
__device__ __forceinline__ float tanhf2(float x) { return 2.0f / (1.0f + __expf(-2.0f * x)) - 1.0f; }

// ---------------- Kernel 1: input projection GEMM (f32x2) — NO elision (R5) ----------------
__global__ void __launch_bounds__(256, 3) proj_kernel(
    const float* __restrict__ x,
    const float* __restrict__ wf, const float* __restrict__ bif, const float* __restrict__ bhf,
    const float* __restrict__ wb, const float* __restrict__ bib, const float* __restrict__ bhb)
{
    __shared__ float sA[32 * 132];
    __shared__ float sB[32 * 68];

    const int dir = blockIdx.z;
    const float* w  = dir ? wb  : wf;
    const float* bi = dir ? bib : bif;
    const float* bh = dir ? bhb : bhf;

    const int tid = threadIdx.x;
    const int bM = blockIdx.x * 128;
    const int bN = blockIdx.y * 64;
    const int ty = tid >> 4;
    const int tx = tid & 15;

    unsigned long long acc[8][2];
#pragma unroll
    for (int i = 0; i < 8; ++i) { acc[i][0] = 0ull; acc[i][1] = 0ull; }

    const int rowL = tid >> 3;
    const int kL   = (tid & 7) << 2;
    const float* xg = x + (size_t)(bM + rowL) * DD + kL;
    const float* wg = w + (size_t)(bN + rowL) * DD + kL;

    const uint32_t sAa = cvta_s(sA) + ty * 32;
    const uint32_t sBa = cvta_s(sB) + tx * 16;

    for (int kt = 0; kt < 8; ++kt) {
        const int k0 = kt * 32;
#pragma unroll
        for (int p = 0; p < 4; ++p) {
            float4 v = *(const float4*)(xg + (size_t)p * 32 * DD + k0);
            int m = rowL + p * 32;
            sA[(kL + 0) * 132 + m] = v.x;
            sA[(kL + 1) * 132 + m] = v.y;
            sA[(kL + 2) * 132 + m] = v.z;
            sA[(kL + 3) * 132 + m] = v.w;
        }
#pragma unroll
        for (int p = 0; p < 2; ++p) {
            float4 v = *(const float4*)(wg + (size_t)p * 32 * DD + k0);
            int n = rowL + p * 32;
            sB[(kL + 0) * 68 + n] = v.x;
            sB[(kL + 1) * 68 + n] = v.y;
            sB[(kL + 2) * 68 + n] = v.z;
            sB[(kL + 3) * 68 + n] = v.w;
        }
        __syncthreads();
#pragma unroll
        for (int kk = 0; kk < 32; ++kk) {
            float a0, a1, a2, a3, a4, a5, a6, a7;
            LDS_V4F32(a0, a1, a2, a3, sAa + kk * 528);
            LDS_V4F32(a4, a5, a6, a7, sAa + kk * 528 + 16);
            unsigned long long b01, b23;
            LDS_V2U64(b01, b23, sBa + kk * 272);
            unsigned long long aa;
            PACK2(aa, a0); FMA2(acc[0][0], aa, b01); FMA2(acc[0][1], aa, b23);
            PACK2(aa, a1); FMA2(acc[1][0], aa, b01); FMA2(acc[1][1], aa, b23);
            PACK2(aa, a2); FMA2(acc[2][0], aa, b01); FMA2(acc[2][1], aa, b23);
            PACK2(aa, a3); FMA2(acc[3][0], aa, b01); FMA2(acc[3][1], aa, b23);
            PACK2(aa, a4); FMA2(acc[4][0], aa, b01); FMA2(acc[4][1], aa, b23);
            PACK2(aa, a5); FMA2(acc[5][0], aa, b01); FMA2(acc[5][1], aa, b23);
            PACK2(aa, a6); FMA2(acc[6][0], aa, b01); FMA2(acc[6][1], aa, b23);
            PACK2(aa, a7); FMA2(acc[7][0], aa, b01); FMA2(acc[7][1], aa, b23);
        }
        __syncthreads();
    }

    float bias[4];
#pragma unroll
    for (int c = 0; c < 4; ++c) {
        int j = bN + tx * 4 + c;
        bias[c] = bi[j] + bh[j];
    }
    float* Gd = g_G + (size_t)dir * BB * TT * G4;
#pragma unroll
    for (int i = 0; i < 8; ++i) {
        int m = bM + ty * 8 + i;
        float c0, c1, c2, c3;
        UNPACK2(c0, c1, acc[i][0]);
        UNPACK2(c2, c3, acc[i][1]);
        float4 o = make_float4(c0 + bias[0], c1 + bias[1], c2 + bias[2], c3 + bias[3]);
        *(float4*)(Gd + (size_t)m * G4 + bN + tx * 4) = o;
    }
}

// ---------------- noop (shifts ncu capture index so rec gets profiled) ----------------
__global__ void noop_kernel() {}

// ---------------- Kernel 2: LSTM recurrence — VERBATIM R5 (best: 8524 us) ----------
#define REC_SMEM_FLOATS (2048 + 1024)
#define REC_SMEM_BYTES  (REC_SMEM_FLOATS * 4)
#define RECV_BYTES      4096u   // 8 ranks * 128 values * 4 B per step

__global__ void __launch_bounds__(256, 1) __cluster_dims__(8, 1, 1)
lstm_rec_kernel(const float* __restrict__ whh_f, const float* __restrict__ whh_b,
                const int* __restrict__ lengths)
{
    extern __shared__ float sm[];
    float* s_h    = sm;            // [2 buf][256 k][4 b]
    float* s_part = sm + 2048;     // [2 kh][128 g][4 b]
    __shared__ __align__(8) unsigned long long s_bar[2];

    cg::cluster_group cluster = cg::this_cluster();
    const int rank = cluster.block_rank();
    const int cidx = blockIdx.x >> 3;
    const int dir  = cidx >> 3;
    const int b0   = (cidx & 7) * 4;
    const int tid  = threadIdx.x;
    const int kh   = tid >> 7;
    const int g    = tid & 127;

    const float* whh = dir ? whh_b : whh_f;

    const int gt = g >> 5, ul = g & 31;
    const int row_g = (gt << 8) + (rank << 5) + ul;

    float4 wreg[32];
    {
        const float4* wrow = (const float4*)(whh + (size_t)row_g * HH + kh * 128);
#pragma unroll
        for (int j = 0; j < 32; ++j) wreg[j] = wrow[j];
    }

    for (int i = tid; i < 2048; i += 256) s_h[i] = 0.0f;

    const uint32_t bar0 = cvta_s(&s_bar[0]);
    const uint32_t bar1 = cvta_s(&s_bar[1]);
    if (tid == 0) {
        MBAR_INIT(bar0, 1);
        MBAR_INIT(bar1, 1);
    }
    __syncthreads();
    cluster.sync();
    if (tid == 0) {
        MBAR_ARRIVE_EXPECT(bar0, RECV_BYTES);
        MBAR_ARRIVE_EXPECT(bar1, RECV_BYTES);
    }

    int L[4];
#pragma unroll
    for (int b = 0; b < 4; ++b) L[b] = lengths[b0 + b];

    const uint32_t sh_u32 = cvta_s(s_h);
    uint32_t rem_h[8], rem_b0[8], rem_b1[8];
#pragma unroll
    for (int r = 0; r < 8; ++r) {
        MAPA(rem_h[r], sh_u32, r);
        MAPA(rem_b0[r], bar0, r);
        MAPA(rem_b1[r], bar1, r);
    }

    const int t2  = g;
    const int ul2 = t2 >> 2, bu = t2 & 3;
    const int ugl = (rank << 5) + ul2;
    const int Lu  = L[bu];
    float c_state = 0.0f;

    const int LA = L[0], LB = L[1], LC = L[2], LD = L[3];

    const float* Gbase = g_G + (size_t)dir * BB * TT * G4;
    float* hbase = g_h + (size_t)dir * BB * TT * HH;

    const uint32_t part_a = cvta_s(s_part) + (kh * 128 + g) * 16;

    uint32_t ph0 = 0, ph1 = 0;
    int cur = 0;
    for (int s = 0; s < TT; ++s) {
        float p0, p1, p2, p3;
        if (kh == 0) {
            int tA = dir ? (s < LA ? LA - 1 - s : s) : s;
            int tB = dir ? (s < LB ? LB - 1 - s : s) : s;
            int tC = dir ? (s < LC ? LC - 1 - s : s) : s;
            int tD = dir ? (s < LD ? LD - 1 - s : s) : s;
            p0 = Gbase[((size_t)(b0 + 0) * TT + tA) * G4 + row_g];
            p1 = Gbase[((size_t)(b0 + 1) * TT + tB) * G4 + row_g];
            p2 = Gbase[((size_t)(b0 + 2) * TT + tC) * G4 + row_g];
            p3 = Gbase[((size_t)(b0 + 3) * TT + tD) * G4 + row_g];
        }

        if (s > 0) {
            if (s & 1) { mbar_wait(bar1, ph1); ph1 ^= 1; if (tid == 0) MBAR_ARRIVE_EXPECT(bar1, RECV_BYTES); }
            else       { mbar_wait(bar0, ph0); ph0 ^= 1; if (tid == 0) MBAR_ARRIVE_EXPECT(bar0, RECV_BYTES); }
        }

        unsigned long long a01e = 0ull, a23e = 0ull, a01o = 0ull, a23o = 0ull;
        uint32_t ha = sh_u32 + (cur << 12) + kh * 2048;
#pragma unroll
        for (int j = 0; j < 32; ++j) {
            float4 wv = wreg[j];
            unsigned long long h01, h23, wd;
            LDS_V2U64(h01, h23, ha);
            PACK2(wd, wv.x); FMA2(a01e, wd, h01); FMA2(a23e, wd, h23);
            LDS_V2U64(h01, h23, ha + 16);
            PACK2(wd, wv.y); FMA2(a01o, wd, h01); FMA2(a23o, wd, h23);
            LDS_V2U64(h01, h23, ha + 32);
            PACK2(wd, wv.z); FMA2(a01e, wd, h01); FMA2(a23e, wd, h23);
            LDS_V2U64(h01, h23, ha + 48);
            PACK2(wd, wv.w); FMA2(a01o, wd, h01); FMA2(a23o, wd, h23);
            ha += 64;
        }
        unsigned long long a01, a23;
        ADD2(a01, a01e, a01o);
        ADD2(a23, a23e, a23o);
        if (kh == 0) {
            unsigned long long gp;
            PACKP(gp, p0, p1); ADD2(a01, a01, gp);
            PACKP(gp, p2, p3); ADD2(a23, a23, gp);
        }
        asm volatile("st.shared.v2.b64 [%0], {%1, %2};" :: "r"(part_a), "l"(a01), "l"(a23) : "memory");
        __syncthreads();

        if (kh == 1) {
            float iv = s_part[(0   + ul2) * 4 + bu] + s_part[512 + (0   + ul2) * 4 + bu];
            float fv = s_part[(32  + ul2) * 4 + bu] + s_part[512 + (32  + ul2) * 4 + bu];
            float gv = s_part[(64  + ul2) * 4 + bu] + s_part[512 + (64  + ul2) * 4 + bu];
            float ov = s_part[(96  + ul2) * 4 + bu] + s_part[512 + (96  + ul2) * 4 + bu];
            float c_new = sigf(fv) * c_state + sigf(iv) * tanhf2(gv);
            float h_new = sigf(ov) * tanhf2(c_new);
            c_state = c_new;

            const int nxt = cur ^ 1;
            const uint32_t off = ((nxt << 10) + (ugl << 2) + bu) * 4;
            const int sb = (s + 1) & 1;
#pragma unroll
            for (int r = 0; r < 8; ++r)
                ST_ASYNC_B32(rem_h[r] + off, h_new, sb ? rem_b1[r] : rem_b0[r]);

            int tt = dir ? (s < Lu ? Lu - 1 - s : s) : s;
            hbase[((size_t)(b0 + bu) * TT + tt) * HH + ugl] = h_new;
        }
        cur ^= 1;
    }
    cluster.sync();
}

// ---------------- Kernel 3: emissions (skip t >= L_b; crf never reads those) ----------------
__global__ void __launch_bounds__(256) emis_kernel(const float* __restrict__ wtag,
                                                   const float* __restrict__ btag,
                                                   const int* __restrict__ lengths)
{
    __shared__ float sw[KK * 512];
    __shared__ float sb[KK];
    for (int i = threadIdx.x; i < KK * 512; i += 256) sw[i] = wtag[i];
    if (threadIdx.x < KK) sb[threadIdx.x] = btag[threadIdx.x];
    __syncthreads();

    const int warp = threadIdx.x >> 5, lane = threadIdx.x & 31;
    const size_t m = (size_t)blockIdx.x * 8 + warp;
    const int bb = (int)(m / TT);
    const int tt = (int)(m % TT);
    if (tt >= lengths[bb] + 4) return;   // crf scan prefetch touches up to L+3

    const float* hf = g_h + m * HH;
    const float* hb = g_h + (size_t)BB * TT * HH + m * HH;

    float acc[KK];
#pragma unroll
    for (int k = 0; k < KK; ++k) acc[k] = 0.0f;
#pragma unroll
    for (int i = 0; i < 8; ++i) {
        int idx = lane + i * 32;
        float a = hf[idx], b2 = hb[idx];
#pragma unroll
        for (int k = 0; k < KK; ++k) {
            acc[k] = fmaf(a,  sw[k * 512 + idx],       acc[k]);
            acc[k] = fmaf(b2, sw[k * 512 + 256 + idx], acc[k]);
        }
    }
#pragma unroll
    for (int k = 0; k < KK; ++k) {
        float v = acc[k];
#pragma unroll
        for (int off = 16; off; off >>= 1) v += __shfl_xor_sync(~0u, v, off);
        if (lane == 0) g_emis[m * KK + k] = v + sb[k];
    }
}

// ---------------- Kernel 4: CRF (scan stops at L — identical math) ----------------
__global__ void crf_kernel(const int* __restrict__ tags, const int* __restrict__ lengths,
                           const float* __restrict__ start_trans,
                           const float* __restrict__ end_trans,
                           const float* __restrict__ trans)
{
    const int b = blockIdx.x;
    const int lane = threadIdx.x & 31;
    const int L = lengths[b];
    const float* E = g_emis + (size_t)b * TT * KK;
    const int* tg = tags + (size_t)b * TT;
    const int j  = lane & 7;
    const int i0 = (lane >> 3) * 2;
    const int i1 = i0 + 1;

    const float tc0 = trans[i0 * KK + j];
    const float tc1 = trans[i1 * KK + j];

    float sc = start_trans[j] + E[j];
    float e1 = E[1 * KK + j], e2 = E[2 * KK + j], e3 = E[3 * KK + j], e4 = E[4 * KK + j];
#pragma unroll 4
    for (int t = 1; t < L; ++t) {       // sc frozen for t >= L → loop to L only
        float e = e1; e1 = e2; e2 = e3; e3 = e4;
        if (t + 4 < TT) e4 = E[(t + 4) * KK + j];
        float s0 = __shfl_sync(~0u, sc, i0) + tc0;
        float s1 = __shfl_sync(~0u, sc, i1) + tc1;
        float pv = __expf(s0 - sc) + __expf(s1 - sc);
        pv += __shfl_xor_sync(~0u, pv, 8);
        pv += __shfl_xor_sync(~0u, pv, 16);
        sc = sc + __logf(pv) + e;
    }

    float z = sc + end_trans[j];
    float mz = z;
#pragma unroll
    for (int off = 4; off; off >>= 1) mz = fmaxf(mz, __shfl_xor_sync(~0u, mz, off));
    float sz = __expf(z - mz);
#pragma unroll
    for (int off = 4; off; off >>= 1) sz += __shfl_xor_sync(~0u, sz, off);
    float logZ = mz + __logf(sz);

    float part = 0.0f;
    for (int t = 1 + lane; t < L; t += 32)
        part += trans[tg[t - 1] * KK + tg[t]] + E[t * KK + tg[t]];
#pragma unroll
    for (int off = 16; off; off >>= 1) part += __shfl_xor_sync(~0u, part, off);

    if (lane == 0) {
        int t0 = tg[0];
        float num = start_trans[t0] + E[t0] + part + end_trans[tg[L - 1]];
        g_res[b] = num - logZ;
    }
}

// ---------------- Kernel 5: finalize ----------------
__global__ void finalize_kernel(float* __restrict__ out)
{
    float v = g_res[threadIdx.x];
#pragma unroll
    for (int off = 16; off; off >>= 1) v += __shfl_xor_sync(~0u, v, off);
    if (threadIdx.x == 0) out[0] = -v / (float)BB;
}

// ---------------- launch ----------------
extern "C" void kernel_launch(void* const* d_in, const int* in_sizes, int n_in,
                              void* d_out, int out_size)
{
    const float* sentences = (const float*)d_in[0];
    const int*   tags      = (const int*)  d_in[1];
    const int*   lengths   = (const int*)  d_in[2];
    const float* w_ih_f = (const float*)d_in[4];
    const float* w_hh_f = (const float*)d_in[5];
    const float* b_ih_f = (const float*)d_in[6];
    const float* b_hh_f = (const float*)d_in[7];
    const float* w_ih_b = (const float*)d_in[8];
    const float* w_hh_b = (const float*)d_in[9];
    const float* b_ih_b = (const float*)d_in[10];
    const float* b_hh_b = (const float*)d_in[11];
    const float* w_tag  = (const float*)d_in[12];
    const float* b_tag  = (const float*)d_in[13];
    const float* start_trans = (const float*)d_in[14];
    const float* end_trans   = (const float*)d_in[15];
    const float* trans       = (const float*)d_in[16];
    float* out = (float*)d_out;

    dim3 pg(512, 16, 2);
    proj_kernel<<<pg, 256>>>(sentences, w_ih_f, b_ih_f, b_hh_f, w_ih_b, b_ih_b, b_hh_b);
    noop_kernel<<<1, 32>>>();
    noop_kernel<<<1, 32>>>();
    lstm_rec_kernel<<<128, 256, REC_SMEM_BYTES>>>(w_hh_f, w_hh_b, lengths);
    emis_kernel<<<(BB * TT) / 8, 256>>>(w_tag, b_tag, lengths);
    crf_kernel<<<BB, 32>>>(tags, lengths, start_trans, end_trans, trans);
    finalize_kernel<<<1, 32>>>(out);
}